// round 16
// baseline (speedup 1.0000x reference)
#include <cuda_runtime.h>
#include <cuda_bf16.h>

#define NUM_USERS 100000
#define NUM_ITEMS 200000
#define NNODES    300000
#define EMB       64
#define NNZ_C     10000000
#define BATCH     8192
#define MASK_WORDS ((NNODES + 31) / 32)
#define SCAN_BLOCKS ((NNODES + 4095) / 4096)   // 74

// bf16 node features: x0 (converted inputs), x1, x2, x3. Row = 64 bf16 = 128 B
// = 16 uint2 per row. 38.4 MB each -> gather source fits easily in L2.
__device__ uint2    g_b0[(size_t)NNODES * 16];
__device__ uint2    g_b1[(size_t)NNODES * 16];
__device__ uint2    g_b2[(size_t)NNODES * 16];
__device__ uint2    g_b3[(size_t)NNODES * 16];
// CSR: (col, val_bits) pairs grouped by row.
__device__ int2     g_pairs[NNZ_C];
__device__ int      g_rowptr[NNODES + 1];
__device__ int      g_cursor[NNODES];
__device__ int      g_counts[NNODES];
__device__ int      g_bsums[SCAN_BLOCKS];
__device__ unsigned g_mask[MASK_WORDS];

__device__ __forceinline__ float4 bf_to_f4(uint2 m) {
    __nv_bfloat162 a = *reinterpret_cast<__nv_bfloat162*>(&m.x);
    __nv_bfloat162 b = *reinterpret_cast<__nv_bfloat162*>(&m.y);
    float2 fa = __bfloat1622float2(a);
    float2 fb = __bfloat1622float2(b);
    return make_float4(fa.x, fa.y, fb.x, fb.y);
}

__device__ __forceinline__ uint2 f4_to_bf(float4 v) {
    __nv_bfloat162 lo = __float22bfloat162_rn(make_float2(v.x, v.y));
    __nv_bfloat162 hi = __float22bfloat162_rn(make_float2(v.z, v.w));
    return make_uint2(*reinterpret_cast<unsigned*>(&lo),
                      *reinterpret_cast<unsigned*>(&hi));
}

// ---------------- preprocessing ----------------

// Convert x0 = concat(ue, ie) to bf16, zero counts + mask. One pass.
__global__ void cvt_zero_kernel(const float4* __restrict__ ue, const float4* __restrict__ ie) {
    int i = blockIdx.x * blockDim.x + threadIdx.x;
    const int total = NNODES * 16;
    if (i >= total) return;
    const int usplit = NUM_USERS * 16;
    float4 v = (i < usplit) ? __ldg(ue + i) : __ldg(ie + (i - usplit));
    g_b0[i] = f4_to_bf(v);
    if (i < NNODES) g_counts[i] = 0;
    if (i < MASK_WORDS) g_mask[i] = 0u;
}

// Histogram of destination rows, 4 edges per thread for MLP.
__global__ void hist_kernel(const int* __restrict__ rows) {
    int base = blockIdx.x * 1024 + threadIdx.x;
    int r[4]; bool ok[4];
    #pragma unroll
    for (int k = 0; k < 4; k++) {
        int e = base + k * 256;
        ok[k] = (e < NNZ_C);
        r[k] = ok[k] ? __ldcs(rows + e) : 0;
    }
    #pragma unroll
    for (int k = 0; k < 4; k++)
        if (ok[k]) atomicAdd(&g_counts[r[k]], 1);
}

// Phase 1: per-block (4096 elems) exclusive scan into g_rowptr, block totals out.
__global__ void scan1_kernel() {
    __shared__ int wsums[32];
    const int tid = threadIdx.x, lane = tid & 31, wid = tid >> 5;
    int idx = blockIdx.x * 4096 + tid * 4;
    int4 c = make_int4(0, 0, 0, 0);
    if (idx < NNODES) c = *(const int4*)(g_counts + idx);   // NNODES % 4 == 0
    int tsum = c.x + c.y + c.z + c.w;

    int v = tsum;
    #pragma unroll
    for (int o = 1; o < 32; o <<= 1) {
        int n = __shfl_up_sync(0xFFFFFFFFu, v, o);
        if (lane >= o) v += n;
    }
    if (lane == 31) wsums[wid] = v;
    __syncthreads();
    if (wid == 0) {
        int wv = wsums[lane];
        #pragma unroll
        for (int o = 1; o < 32; o <<= 1) {
            int n = __shfl_up_sync(0xFFFFFFFFu, wv, o);
            if (lane >= o) wv += n;
        }
        wsums[lane] = wv;
    }
    __syncthreads();
    int excl = v - tsum + (wid ? wsums[wid - 1] : 0);
    if (idx < NNODES) {
        int4 o4;
        o4.x = excl;
        o4.y = excl + c.x;
        o4.z = excl + c.x + c.y;
        o4.w = excl + c.x + c.y + c.z;
        *(int4*)(g_rowptr + idx) = o4;
    }
    if (tid == 1023) g_bsums[blockIdx.x] = excl + tsum;  // block total
}

// Phase 2: tiny scan of the 74 block totals (exclusive), write grand total.
__global__ void scan2_kernel() {
    __shared__ int s[SCAN_BLOCKS + 1];
    int tid = threadIdx.x;
    if (tid < SCAN_BLOCKS) s[tid + 1] = g_bsums[tid];
    if (tid == 0) s[0] = 0;
    __syncthreads();
    if (tid == 0) {
        for (int i = 1; i <= SCAN_BLOCKS; i++) s[i] += s[i - 1];
        g_rowptr[NNODES] = s[SCAN_BLOCKS];   // == NNZ
    }
    __syncthreads();
    if (tid < SCAN_BLOCKS) g_bsums[tid] = s[tid];
}

// Phase 3: add block offsets; mirror rowptr into cursor.
__global__ void scan3_kernel() {
    int idx = blockIdx.x * 4096 + threadIdx.x * 4;
    if (idx >= NNODES) return;
    int off = __ldg(&g_bsums[blockIdx.x]);
    int4 r = *(int4*)(g_rowptr + idx);
    r.x += off; r.y += off; r.z += off; r.w += off;
    *(int4*)(g_rowptr + idx) = r;
    *(int4*)(g_cursor + idx) = r;
}

// Scatter edges into CSR order, 4 edges per thread (batched loads first).
__global__ void build_kernel(const int* __restrict__ rows, const int* __restrict__ cols,
                             const float* __restrict__ vals) {
    int base = blockIdx.x * 1024 + threadIdx.x;
    int r[4], c[4]; float v[4]; bool ok[4];
    #pragma unroll
    for (int k = 0; k < 4; k++) {
        int e = base + k * 256;
        ok[k] = (e < NNZ_C);
        if (ok[k]) { r[k] = __ldcs(rows + e); c[k] = __ldcs(cols + e); v[k] = __ldcs(vals + e); }
    }
    int pos[4];
    #pragma unroll
    for (int k = 0; k < 4; k++)
        if (ok[k]) pos[k] = atomicAdd(&g_cursor[r[k]], 1);
    #pragma unroll
    for (int k = 0; k < 4; k++)
        if (ok[k]) g_pairs[pos[k]] = make_int2(c[k], __float_as_int(v[k]));
}

__global__ void mask_set_kernel(const int* __restrict__ u, const int* __restrict__ it) {
    int t = blockIdx.x * blockDim.x + threadIdx.x;
    if (t >= 2 * BATCH) return;
    int r = (t < BATCH) ? __ldg(u + t) : (NUM_USERS + __ldg(it + (t - BATCH)));
    atomicOr(&g_mask[r >> 5], 1u << (r & 31));
}

// ---------------- CSR SpMM (bf16 in, bf16 out): one warp per row ----------------
// Half-warps handle interleaved edges; 16 lanes x uint2 = 128 B source row.
template <int MASKED>
__global__ void __launch_bounds__(256) csr_spmm(const uint2* __restrict__ x,
                                                uint2* __restrict__ xn) {
    int w = (blockIdx.x * 256 + threadIdx.x) >> 5;   // row; grid covers NNODES exactly
    int lane = threadIdx.x & 31;
    int sub = lane >> 4, l16 = lane & 15;

    if (MASKED) {
        if (!((__ldg(&g_mask[w >> 5]) >> (w & 31)) & 1u)) return;   // warp-uniform
    }

    int start = __ldg(&g_rowptr[w]);
    int end   = __ldg(&g_rowptr[w + 1]);

    float4 acc = make_float4(0.f, 0.f, 0.f, 0.f);
    int e = start + sub;

    // 8 edges per warp-iteration (4 per half): 4 independent gathers in flight.
    for (; e + 6 < end; e += 8) {
        int2 p0 = __ldg((const int2*)g_pairs + e);
        int2 p1 = __ldg((const int2*)g_pairs + e + 2);
        int2 p2 = __ldg((const int2*)g_pairs + e + 4);
        int2 p3 = __ldg((const int2*)g_pairs + e + 6);
        float4 m0 = bf_to_f4(__ldg(x + (size_t)p0.x * 16 + l16));
        float4 m1 = bf_to_f4(__ldg(x + (size_t)p1.x * 16 + l16));
        float4 m2 = bf_to_f4(__ldg(x + (size_t)p2.x * 16 + l16));
        float4 m3 = bf_to_f4(__ldg(x + (size_t)p3.x * 16 + l16));
        float v0 = __int_as_float(p0.y), v1 = __int_as_float(p1.y);
        float v2 = __int_as_float(p2.y), v3 = __int_as_float(p3.y);
        acc.x += m0.x * v0 + m1.x * v1 + m2.x * v2 + m3.x * v3;
        acc.y += m0.y * v0 + m1.y * v1 + m2.y * v2 + m3.y * v3;
        acc.z += m0.z * v0 + m1.z * v1 + m2.z * v2 + m3.z * v3;
        acc.w += m0.w * v0 + m1.w * v1 + m2.w * v2 + m3.w * v3;
    }
    for (; e < end; e += 2) {
        int2 p = __ldg((const int2*)g_pairs + e);
        float4 m = bf_to_f4(__ldg(x + (size_t)p.x * 16 + l16));
        float v = __int_as_float(p.y);
        acc.x += m.x * v; acc.y += m.y * v; acc.z += m.z * v; acc.w += m.w * v;
    }

    acc.x += __shfl_xor_sync(0xFFFFFFFFu, acc.x, 16);
    acc.y += __shfl_xor_sync(0xFFFFFFFFu, acc.y, 16);
    acc.z += __shfl_xor_sync(0xFFFFFFFFu, acc.z, 16);
    acc.w += __shfl_xor_sync(0xFFFFFFFFu, acc.w, 16);

    if (sub == 0) __stcs(xn + (size_t)w * 16 + l16, f4_to_bf(acc));
}

// ---------------- final dot ----------------
// One warp per (u,i) pair; lane covers 2 dims. x0 read fp32 (exact), x1..x3 bf16.
__global__ void dot_kernel(const float* __restrict__ ue, const float* __restrict__ ie,
                           const int* __restrict__ u, const int* __restrict__ it,
                           float* __restrict__ out) {
    int w = (int)(((size_t)blockIdx.x * blockDim.x + threadIdx.x) >> 5);
    int lane = threadIdx.x & 31;
    if (w >= BATCH) return;

    int ur = __ldg(u + w);
    int il = __ldg(it + w);
    int ir = NUM_USERS + il;

    const __nv_bfloat162* b1 = (const __nv_bfloat162*)g_b1;  // row stride = 32
    const __nv_bfloat162* b2 = (const __nv_bfloat162*)g_b2;
    const __nv_bfloat162* b3 = (const __nv_bfloat162*)g_b3;

    float2 p0 = ((const float2*)(ue + (size_t)ur * EMB))[lane];
    float2 p1 = __bfloat1622float2(__ldg(b1 + (size_t)ur * 32 + lane));
    float2 p2 = __bfloat1622float2(__ldg(b2 + (size_t)ur * 32 + lane));
    float2 p3 = __bfloat1622float2(__ldg(b3 + (size_t)ur * 32 + lane));

    float2 q0 = ((const float2*)(ie + (size_t)il * EMB))[lane];
    float2 q1 = __bfloat1622float2(__ldg(b1 + (size_t)ir * 32 + lane));
    float2 q2 = __bfloat1622float2(__ldg(b2 + (size_t)ir * 32 + lane));
    float2 q3 = __bfloat1622float2(__ldg(b3 + (size_t)ir * 32 + lane));

    float px = p0.x + p1.x + p2.x + p3.x;
    float py = p0.y + p1.y + p2.y + p3.y;
    float qx = q0.x + q1.x + q2.x + q3.x;
    float qy = q0.y + q1.y + q2.y + q3.y;

    float s = px * qx + py * qy;
    #pragma unroll
    for (int off = 16; off > 0; off >>= 1)
        s += __shfl_xor_sync(0xFFFFFFFFu, s, off);

    if (lane == 0) out[w] = s * 0.0625f;
}

// ---------------- launch ----------------

extern "C" void kernel_launch(void* const* d_in, const int* in_sizes, int n_in,
                              void* d_out, int out_size) {
    const float4* ue   = (const float4*)d_in[0];
    const float4* ie   = (const float4*)d_in[1];
    const float*  vals = (const float*)d_in[2];
    const int*    rows = (const int*)d_in[3];
    const int*    cols = (const int*)d_in[4];
    const int*    uidx = (const int*)d_in[5];
    const int*    iidx = (const int*)d_in[6];
    float*        out  = (float*)d_out;

    uint2 *b0, *b1, *b2, *b3;
    cudaGetSymbolAddress((void**)&b0, g_b0);
    cudaGetSymbolAddress((void**)&b1, g_b1);
    cudaGetSymbolAddress((void**)&b2, g_b2);
    cudaGetSymbolAddress((void**)&b3, g_b3);

    const int cvtblocks = (NNODES * 16 + 255) / 256;   // 18750
    const int e4blocks  = (NNZ_C + 1023) / 1024;       // 9766
    const int sblocks   = NNODES / 8;                  // 37500 (exact)

    cvt_zero_kernel<<<cvtblocks, 256>>>(ue, ie);
    hist_kernel<<<e4blocks, 256>>>(rows);
    scan1_kernel<<<SCAN_BLOCKS, 1024>>>();
    scan2_kernel<<<1, 128>>>();
    scan3_kernel<<<SCAN_BLOCKS, 1024>>>();
    build_kernel<<<e4blocks, 256>>>(rows, cols, vals);
    mask_set_kernel<<<(2 * BATCH + 255) / 256, 256>>>(uidx, iidx);

    csr_spmm<0><<<sblocks, 256>>>(b0, b1);   // x0 -> x1
    csr_spmm<0><<<sblocks, 256>>>(b1, b2);   // x1 -> x2
    csr_spmm<1><<<sblocks, 256>>>(b2, b3);   // x2 -> x3 (masked rows only)

    dot_kernel<<<BATCH / 8, 256>>>((const float*)ue, (const float*)ie, uidx, iidx, out);
}

// round 17
// speedup vs baseline: 1.0069x; 1.0069x over previous
#include <cuda_runtime.h>
#include <cuda_bf16.h>

#define NUM_USERS 100000
#define NUM_ITEMS 200000
#define NNODES    300000
#define EMB       64
#define NNZ_C     10000000
#define BATCH     8192
#define MASK_WORDS ((NNODES + 31) / 32)
#define SCAN_BLOCKS ((NNODES + 4095) / 4096)   // 74

// bf16 node features: x0 (converted inputs), x1, x2, x3. Row = 64 bf16 = 128 B
// = 16 uint2 per row. 38.4 MB each -> gather source fits easily in L2.
__device__ uint2    g_b0[(size_t)NNODES * 16];
__device__ uint2    g_b1[(size_t)NNODES * 16];
__device__ uint2    g_b2[(size_t)NNODES * 16];
__device__ uint2    g_b3[(size_t)NNODES * 16];
// CSR: (col, val_bits) pairs grouped by row.
__device__ int2     g_pairs[NNZ_C];
__device__ int      g_rowptr[NNODES + 1];
__device__ int      g_cursor[NNODES];
__device__ int      g_counts[NNODES];
__device__ int      g_bsums[SCAN_BLOCKS];
__device__ unsigned g_mask[MASK_WORDS];

__device__ __forceinline__ float4 bf_to_f4(uint2 m) {
    __nv_bfloat162 a = *reinterpret_cast<__nv_bfloat162*>(&m.x);
    __nv_bfloat162 b = *reinterpret_cast<__nv_bfloat162*>(&m.y);
    float2 fa = __bfloat1622float2(a);
    float2 fb = __bfloat1622float2(b);
    return make_float4(fa.x, fa.y, fb.x, fb.y);
}

__device__ __forceinline__ uint2 f4_to_bf(float4 v) {
    __nv_bfloat162 lo = __float22bfloat162_rn(make_float2(v.x, v.y));
    __nv_bfloat162 hi = __float22bfloat162_rn(make_float2(v.z, v.w));
    return make_uint2(*reinterpret_cast<unsigned*>(&lo),
                      *reinterpret_cast<unsigned*>(&hi));
}

// ---------------- preprocessing ----------------

// Convert x0 = concat(ue, ie) to bf16, zero counts + mask. One pass.
__global__ void cvt_zero_kernel(const float4* __restrict__ ue, const float4* __restrict__ ie) {
    int i = blockIdx.x * blockDim.x + threadIdx.x;
    const int total = NNODES * 16;
    if (i >= total) return;
    const int usplit = NUM_USERS * 16;
    float4 v = (i < usplit) ? __ldg(ue + i) : __ldg(ie + (i - usplit));
    g_b0[i] = f4_to_bf(v);
    if (i < NNODES) g_counts[i] = 0;
    if (i < MASK_WORDS) g_mask[i] = 0u;
}

// Histogram of destination rows, 4 edges per thread for MLP.
__global__ void hist_kernel(const int* __restrict__ rows) {
    int base = blockIdx.x * 1024 + threadIdx.x;
    int r[4]; bool ok[4];
    #pragma unroll
    for (int k = 0; k < 4; k++) {
        int e = base + k * 256;
        ok[k] = (e < NNZ_C);
        r[k] = ok[k] ? __ldcs(rows + e) : 0;
    }
    #pragma unroll
    for (int k = 0; k < 4; k++)
        if (ok[k]) atomicAdd(&g_counts[r[k]], 1);
}

// Phase 1: per-block (4096 elems) exclusive scan into g_rowptr, block totals out.
__global__ void scan1_kernel() {
    __shared__ int wsums[32];
    const int tid = threadIdx.x, lane = tid & 31, wid = tid >> 5;
    int idx = blockIdx.x * 4096 + tid * 4;
    int4 c = make_int4(0, 0, 0, 0);
    if (idx < NNODES) c = *(const int4*)(g_counts + idx);   // NNODES % 4 == 0
    int tsum = c.x + c.y + c.z + c.w;

    int v = tsum;
    #pragma unroll
    for (int o = 1; o < 32; o <<= 1) {
        int n = __shfl_up_sync(0xFFFFFFFFu, v, o);
        if (lane >= o) v += n;
    }
    if (lane == 31) wsums[wid] = v;
    __syncthreads();
    if (wid == 0) {
        int wv = wsums[lane];
        #pragma unroll
        for (int o = 1; o < 32; o <<= 1) {
            int n = __shfl_up_sync(0xFFFFFFFFu, wv, o);
            if (lane >= o) wv += n;
        }
        wsums[lane] = wv;
    }
    __syncthreads();
    int excl = v - tsum + (wid ? wsums[wid - 1] : 0);
    if (idx < NNODES) {
        int4 o4;
        o4.x = excl;
        o4.y = excl + c.x;
        o4.z = excl + c.x + c.y;
        o4.w = excl + c.x + c.y + c.z;
        *(int4*)(g_rowptr + idx) = o4;
    }
    if (tid == 1023) g_bsums[blockIdx.x] = excl + tsum;  // block total
}

// Phase 2: tiny scan of the 74 block totals (exclusive), write grand total.
__global__ void scan2_kernel() {
    __shared__ int s[SCAN_BLOCKS + 1];
    int tid = threadIdx.x;
    if (tid < SCAN_BLOCKS) s[tid + 1] = g_bsums[tid];
    if (tid == 0) s[0] = 0;
    __syncthreads();
    if (tid == 0) {
        for (int i = 1; i <= SCAN_BLOCKS; i++) s[i] += s[i - 1];
        g_rowptr[NNODES] = s[SCAN_BLOCKS];   // == NNZ
    }
    __syncthreads();
    if (tid < SCAN_BLOCKS) g_bsums[tid] = s[tid];
}

// Phase 3: add block offsets; mirror rowptr into cursor.
__global__ void scan3_kernel() {
    int idx = blockIdx.x * 4096 + threadIdx.x * 4;
    if (idx >= NNODES) return;
    int off = __ldg(&g_bsums[blockIdx.x]);
    int4 r = *(int4*)(g_rowptr + idx);
    r.x += off; r.y += off; r.z += off; r.w += off;
    *(int4*)(g_rowptr + idx) = r;
    *(int4*)(g_cursor + idx) = r;
}

// Scatter edges into CSR order, 4 edges per thread (batched loads first).
__global__ void build_kernel(const int* __restrict__ rows, const int* __restrict__ cols,
                             const float* __restrict__ vals) {
    int base = blockIdx.x * 1024 + threadIdx.x;
    int r[4], c[4]; float v[4]; bool ok[4];
    #pragma unroll
    for (int k = 0; k < 4; k++) {
        int e = base + k * 256;
        ok[k] = (e < NNZ_C);
        if (ok[k]) { r[k] = __ldcs(rows + e); c[k] = __ldcs(cols + e); v[k] = __ldcs(vals + e); }
    }
    int pos[4];
    #pragma unroll
    for (int k = 0; k < 4; k++)
        if (ok[k]) pos[k] = atomicAdd(&g_cursor[r[k]], 1);
    #pragma unroll
    for (int k = 0; k < 4; k++)
        if (ok[k]) g_pairs[pos[k]] = make_int2(c[k], __float_as_int(v[k]));
}

__global__ void mask_set_kernel(const int* __restrict__ u, const int* __restrict__ it) {
    int t = blockIdx.x * blockDim.x + threadIdx.x;
    if (t >= 2 * BATCH) return;
    int r = (t < BATCH) ? __ldg(u + t) : (NUM_USERS + __ldg(it + (t - BATCH)));
    atomicOr(&g_mask[r >> 5], 1u << (r & 31));
}

// ---------------- CSR SpMM (bf16 in, bf16 out): one warp per row ----------------
// Half-warps handle interleaved edges; 16 lanes x uint2 = 128 B source row.
template <int MASKED>
__global__ void __launch_bounds__(256) csr_spmm(const uint2* __restrict__ x,
                                                uint2* __restrict__ xn) {
    int w = (blockIdx.x * 256 + threadIdx.x) >> 5;   // row; grid covers NNODES exactly
    int lane = threadIdx.x & 31;
    int sub = lane >> 4, l16 = lane & 15;

    if (MASKED) {
        if (!((__ldg(&g_mask[w >> 5]) >> (w & 31)) & 1u)) return;   // warp-uniform
    }

    int start = __ldg(&g_rowptr[w]);
    int end   = __ldg(&g_rowptr[w + 1]);

    float4 acc = make_float4(0.f, 0.f, 0.f, 0.f);
    int e = start + sub;

    // 8 edges per warp-iteration (4 per half): 4 independent gathers in flight.
    for (; e + 6 < end; e += 8) {
        int2 p0 = __ldg((const int2*)g_pairs + e);
        int2 p1 = __ldg((const int2*)g_pairs + e + 2);
        int2 p2 = __ldg((const int2*)g_pairs + e + 4);
        int2 p3 = __ldg((const int2*)g_pairs + e + 6);
        float4 m0 = bf_to_f4(__ldg(x + (size_t)p0.x * 16 + l16));
        float4 m1 = bf_to_f4(__ldg(x + (size_t)p1.x * 16 + l16));
        float4 m2 = bf_to_f4(__ldg(x + (size_t)p2.x * 16 + l16));
        float4 m3 = bf_to_f4(__ldg(x + (size_t)p3.x * 16 + l16));
        float v0 = __int_as_float(p0.y), v1 = __int_as_float(p1.y);
        float v2 = __int_as_float(p2.y), v3 = __int_as_float(p3.y);
        acc.x += m0.x * v0 + m1.x * v1 + m2.x * v2 + m3.x * v3;
        acc.y += m0.y * v0 + m1.y * v1 + m2.y * v2 + m3.y * v3;
        acc.z += m0.z * v0 + m1.z * v1 + m2.z * v2 + m3.z * v3;
        acc.w += m0.w * v0 + m1.w * v1 + m2.w * v2 + m3.w * v3;
    }
    for (; e < end; e += 2) {
        int2 p = __ldg((const int2*)g_pairs + e);
        float4 m = bf_to_f4(__ldg(x + (size_t)p.x * 16 + l16));
        float v = __int_as_float(p.y);
        acc.x += m.x * v; acc.y += m.y * v; acc.z += m.z * v; acc.w += m.w * v;
    }

    acc.x += __shfl_xor_sync(0xFFFFFFFFu, acc.x, 16);
    acc.y += __shfl_xor_sync(0xFFFFFFFFu, acc.y, 16);
    acc.z += __shfl_xor_sync(0xFFFFFFFFu, acc.z, 16);
    acc.w += __shfl_xor_sync(0xFFFFFFFFu, acc.w, 16);

    if (sub == 0) __stcs(xn + (size_t)w * 16 + l16, f4_to_bf(acc));
}

// ---------------- final dot ----------------
// One warp per (u,i) pair; lane covers 2 dims. x0 read fp32 (exact), x1..x3 bf16.
__global__ void dot_kernel(const float* __restrict__ ue, const float* __restrict__ ie,
                           const int* __restrict__ u, const int* __restrict__ it,
                           float* __restrict__ out) {
    int w = (int)(((size_t)blockIdx.x * blockDim.x + threadIdx.x) >> 5);
    int lane = threadIdx.x & 31;
    if (w >= BATCH) return;

    int ur = __ldg(u + w);
    int il = __ldg(it + w);
    int ir = NUM_USERS + il;

    const __nv_bfloat162* b1 = (const __nv_bfloat162*)g_b1;  // row stride = 32
    const __nv_bfloat162* b2 = (const __nv_bfloat162*)g_b2;
    const __nv_bfloat162* b3 = (const __nv_bfloat162*)g_b3;

    float2 p0 = ((const float2*)(ue + (size_t)ur * EMB))[lane];
    float2 p1 = __bfloat1622float2(__ldg(b1 + (size_t)ur * 32 + lane));
    float2 p2 = __bfloat1622float2(__ldg(b2 + (size_t)ur * 32 + lane));
    float2 p3 = __bfloat1622float2(__ldg(b3 + (size_t)ur * 32 + lane));

    float2 q0 = ((const float2*)(ie + (size_t)il * EMB))[lane];
    float2 q1 = __bfloat1622float2(__ldg(b1 + (size_t)ir * 32 + lane));
    float2 q2 = __bfloat1622float2(__ldg(b2 + (size_t)ir * 32 + lane));
    float2 q3 = __bfloat1622float2(__ldg(b3 + (size_t)ir * 32 + lane));

    float px = p0.x + p1.x + p2.x + p3.x;
    float py = p0.y + p1.y + p2.y + p3.y;
    float qx = q0.x + q1.x + q2.x + q3.x;
    float qy = q0.y + q1.y + q2.y + q3.y;

    float s = px * qx + py * qy;
    #pragma unroll
    for (int off = 16; off > 0; off >>= 1)
        s += __shfl_xor_sync(0xFFFFFFFFu, s, off);

    if (lane == 0) out[w] = s * 0.0625f;
}

// ---------------- launch ----------------

extern "C" void kernel_launch(void* const* d_in, const int* in_sizes, int n_in,
                              void* d_out, int out_size) {
    const float4* ue   = (const float4*)d_in[0];
    const float4* ie   = (const float4*)d_in[1];
    const float*  vals = (const float*)d_in[2];
    const int*    rows = (const int*)d_in[3];
    const int*    cols = (const int*)d_in[4];
    const int*    uidx = (const int*)d_in[5];
    const int*    iidx = (const int*)d_in[6];
    float*        out  = (float*)d_out;

    uint2 *b0, *b1, *b2, *b3;
    cudaGetSymbolAddress((void**)&b0, g_b0);
    cudaGetSymbolAddress((void**)&b1, g_b1);
    cudaGetSymbolAddress((void**)&b2, g_b2);
    cudaGetSymbolAddress((void**)&b3, g_b3);

    const int cvtblocks = (NNODES * 16 + 255) / 256;   // 18750
    const int e4blocks  = (NNZ_C + 1023) / 1024;       // 9766
    const int sblocks   = NNODES / 8;                  // 37500 (exact)

    cvt_zero_kernel<<<cvtblocks, 256>>>(ue, ie);
    hist_kernel<<<e4blocks, 256>>>(rows);
    scan1_kernel<<<SCAN_BLOCKS, 1024>>>();
    scan2_kernel<<<1, 128>>>();
    scan3_kernel<<<SCAN_BLOCKS, 1024>>>();
    build_kernel<<<e4blocks, 256>>>(rows, cols, vals);
    mask_set_kernel<<<(2 * BATCH + 255) / 256, 256>>>(uidx, iidx);

    csr_spmm<0><<<sblocks, 256>>>(b0, b1);   // x0 -> x1
    csr_spmm<0><<<sblocks, 256>>>(b1, b2);   // x1 -> x2
    csr_spmm<1><<<sblocks, 256>>>(b2, b3);   // x2 -> x3 (masked rows only)

    dot_kernel<<<BATCH / 8, 256>>>((const float*)ue, (const float*)ie, uidx, iidx, out);
}